// round 12
// baseline (speedup 1.0000x reference)
#include <cuda_runtime.h>
#include <cuda_bf16.h>
#include <cstdint>

#define DEV_INLINE __device__ __forceinline__

// ---------------- problem sizes (fixed) ----------------
#define DD    2048
#define SD    512
#define MROWS 16384          // B*N = 4*4096
#define KTOT  4096           // concatenated K (attn 2048 | hyb 2048)
#define BK    64             // K elements per pipeline chunk (bf16)
#define NK_CHUNKS 64         // 4096/64
#define STAGE_BYTES 32768    // A tile 16KB + B tile 16KB
#define DYN_SMEM (3 * STAGE_BYTES)

// ---------------- device scratch (static, no allocs) ----------------
__device__ __nv_bfloat16 g_A [(size_t)MROWS * KTOT];  // [m][attn 0..2047 | hyb 2048..4095]
__device__ __nv_bfloat16 g_Wc[(size_t)DD * KTOT];     // permuted combined weights [p][k]
__device__ float         g_bias[DD];                  // permuted combined bias

struct SmallMats {
    float pre_a[4][4], pre_h[4][4];
    float ca_mix[4][4], ch_mix[4][4];   // alpha*sc*post (t,s)
    float Rw[4][4];                     // combined residual mix (s,t)
    float alpha;
};
__device__ SmallMats g_sm;

// ---------------- PTX helpers (base ISA only: sm_80+) ----------------
DEV_INLINE uint32_t smem_u32(const void* p) {
    uint32_t a;
    asm("{ .reg .u64 t; cvta.to.shared.u64 t, %1; cvt.u32.u64 %0, t; }" : "=r"(a) : "l"(p));
    return a;
}
#define SW128(o) ((o) ^ ((((uint32_t)(o)) >> 3) & 0x70u))

DEV_INLINE void cp_async16(uint32_t dst, const void* src) {
    asm volatile("cp.async.cg.shared.global [%0], [%1], 16;" :: "r"(dst), "l"(src));
}
DEV_INLINE void cp_commit() { asm volatile("cp.async.commit_group;" ::: "memory"); }
template<int N> DEV_INLINE void cp_wait() {
    asm volatile("cp.async.wait_group %0;" :: "n"(N) : "memory");
}
DEV_INLINE void ldm_x4(uint32_t* r, uint32_t addr) {
    asm volatile("ldmatrix.sync.aligned.m8n8.x4.shared.b16 {%0,%1,%2,%3}, [%4];"
                 : "=r"(r[0]), "=r"(r[1]), "=r"(r[2]), "=r"(r[3]) : "r"(addr));
}
DEV_INLINE void mma16816(float* d, const uint32_t* a, uint32_t b0, uint32_t b1) {
    asm volatile(
        "mma.sync.aligned.m16n8k16.row.col.f32.bf16.bf16.f32 "
        "{%0,%1,%2,%3}, {%4,%5,%6,%7}, {%8,%9}, {%0,%1,%2,%3};"
        : "+f"(d[0]), "+f"(d[1]), "+f"(d[2]), "+f"(d[3])
        : "r"(a[0]), "r"(a[1]), "r"(a[2]), "r"(a[3]), "r"(b0), "r"(b1));
}

// ---------------- small 4x4 matrices + combined bias (one kernel) ----------------
DEV_INLINE void softmax4(const float* L, float O[4][4]) {
    for (int s = 0; s < 4; s++) {
        float mx = L[s*4];
        for (int t = 1; t < 4; t++) mx = fmaxf(mx, L[s*4+t]);
        float sum = 0.f, e[4];
        for (int t = 0; t < 4; t++) { e[t] = expf(L[s*4+t] - mx); sum += e[t]; }
        float inv = 1.f / sum;
        for (int t = 0; t < 4; t++) O[s][t] = e[t] * inv;
    }
}
DEV_INLINE void sinkhorn4(const float* L, float P[4][4]) {
    float mx = L[0];
    for (int i = 1; i < 16; i++) mx = fmaxf(mx, L[i]);
    for (int s = 0; s < 4; s++)
        for (int t = 0; t < 4; t++) P[s][t] = expf(L[s*4+t] - mx);
    for (int it = 0; it < 20; it++) {
        for (int s = 0; s < 4; s++) {
            float rs = P[s][0] + P[s][1] + P[s][2] + P[s][3];
            float inv = 1.f / (rs + 1e-8f);
            for (int t = 0; t < 4; t++) P[s][t] *= inv;
        }
        for (int t = 0; t < 4; t++) {
            float cs = P[0][t] + P[1][t] + P[2][t] + P[3][t];
            float inv = 1.f / (cs + 1e-8f);
            for (int s = 0; s < 4; s++) P[s][t] *= inv;
        }
    }
}
__global__ void __launch_bounds__(256) small_kernel(
        const float* pa, const float* ph,
        const float* ra, const float* po_a, const float* sa,
        const float* rh, const float* po_h, const float* sh,
        const float* cm, const float* ba, const float* bh) {
    __shared__ SmallMats sm;
    if (threadIdx.x == 0) {
        float post_a[4][4], post_h[4][4], res_a[4][4], res_h[4][4];
        softmax4(pa,   sm.pre_a);
        softmax4(ph,   sm.pre_h);
        softmax4(po_a, post_a);
        softmax4(po_h, post_h);
        sinkhorn4(ra,  res_a);
        sinkhorn4(rh,  res_h);
        float alpha = 1.f / (1.f + expf(-cm[0]));
        sm.alpha = alpha;
        float beta = 1.f - alpha;
        for (int t = 0; t < 4; t++)
            for (int s = 0; s < 4; s++) {
                sm.ca_mix[t][s] = alpha * sa[t] * post_a[t][s];
                sm.ch_mix[t][s] = beta  * sh[t] * post_h[t][s];
                sm.Rw[s][t]     = alpha * res_a[s][t] + beta * res_h[s][t];
            }
        g_sm = sm;
    }
    __syncthreads();
    // combined permuted bias: p = (dd>>5)*128 + t*32 + (dd&31)
    for (int p = threadIdx.x; p < DD; p += 256) {
        int t = (p >> 5) & 3;
        int dd = ((p >> 7) << 5) + (p & 31);
        float v = 0.f;
#pragma unroll
        for (int s = 0; s < 4; s++)
            v += sm.ca_mix[t][s] * ba[s * SD + dd] + sm.ch_mix[t][s] * bh[s * SD + dd];
        g_bias[p] = v;
    }
}

// ---------------- W transpose + post-mix fold + bf16 quantize ----------------
// One block handles (k-block, dd-block, z) and emits ALL 4 t-streams.
__global__ void wtrans_kernel(const float* __restrict__ Wa, const float* __restrict__ Wh) {
    __shared__ float t4[4][32][33];
    const int z = blockIdx.z;
    const float* W = z ? Wh : Wa;
    const int k0  = blockIdx.x * 32;
    const int dd0 = blockIdx.y * 32;
    const int tx = threadIdx.x, ty = threadIdx.y;
#pragma unroll
    for (int s = 0; s < 4; s++)
#pragma unroll
        for (int j = 0; j < 32; j += 8)
            t4[s][ty + j][tx] = W[(size_t)(k0 + ty + j) * DD + s * SD + dd0 + tx];
    __syncthreads();
#pragma unroll
    for (int t = 0; t < 4; t++) {
        float c[4];
#pragma unroll
        for (int s = 0; s < 4; s++)
            c[s] = z ? g_sm.ch_mix[t][s] : g_sm.ca_mix[t][s];
        const size_t prow = (size_t)(blockIdx.y * 128 + t * 32);
#pragma unroll
        for (int j = 0; j < 32; j += 8) {
            int pi = ty + j;
            float v = 0.f;
#pragma unroll
            for (int s = 0; s < 4; s++) v += c[s] * t4[s][tx][pi];
            g_Wc[(prow + pi) * KTOT + z * DD + k0 + tx] = __float2bfloat16(v);
        }
    }
}

// ---------------- fused LayerNorm + H_pre mixes -> bf16 GEMM inputs ----------------
DEV_INLINE uint32_t packbf2(float a, float b) {
    __nv_bfloat162 t = __floats2bfloat162_rn(a, b);
    return *reinterpret_cast<uint32_t*>(&t);
}
__global__ void __launch_bounds__(256) pre_kernel(const float* __restrict__ x,
                                                  const float* __restrict__ gamma,
                                                  const float* __restrict__ beta) {
    __shared__ float sred[18];
    const int tid = threadIdx.x;
    const float* xr = x + (size_t)blockIdx.x * DD;
    const int d0 = tid * 2;

    float2 xv[4];
    float s1 = 0.f, s2 = 0.f;
#pragma unroll
    for (int s = 0; s < 4; s++) {
        xv[s] = *(const float2*)(xr + s * SD + d0);
        s1 += xv[s].x + xv[s].y;
        s2 += xv[s].x * xv[s].x + xv[s].y * xv[s].y;
    }
#pragma unroll
    for (int off = 16; off > 0; off >>= 1) {
        s1 += __shfl_xor_sync(0xffffffffu, s1, off);
        s2 += __shfl_xor_sync(0xffffffffu, s2, off);
    }
    if ((tid & 31) == 0) { sred[tid >> 5] = s1; sred[8 + (tid >> 5)] = s2; }
    __syncthreads();
    if (tid == 0) {
        float a = 0.f, b = 0.f;
        for (int w = 0; w < 8; w++) { a += sred[w]; b += sred[8 + w]; }
        float mu = a * (1.f / DD);
        float var = b * (1.f / DD) - mu * mu;
        sred[16] = mu;
        sred[17] = rsqrtf(var + 1e-5f);
    }
    __syncthreads();
    const float mu = sred[16], rstd = sred[17];

    float n0[4], n1[4];
#pragma unroll
    for (int s = 0; s < 4; s++) {
        float2 gv = __ldg((const float2*)(gamma + s * SD + d0));
        float2 bv = __ldg((const float2*)(beta  + s * SD + d0));
        n0[s] = (xv[s].x - mu) * rstd * gv.x + bv.x;
        n1[s] = (xv[s].y - mu) * rstd * gv.y + bv.y;
    }

    __nv_bfloat16* arow = g_A + (size_t)blockIdx.x * KTOT;
#pragma unroll
    for (int t = 0; t < 4; t++) {
        float a0 = 0.f, a1 = 0.f, h0 = 0.f, h1 = 0.f;
#pragma unroll
        for (int s = 0; s < 4; s++) {
            float wa = g_sm.pre_a[s][t];
            float wh = g_sm.pre_h[s][t];
            a0 += wa * n0[s];  a1 += wa * n1[s];
            h0 += wh * xv[s].x; h1 += wh * xv[s].y;
        }
        *(uint32_t*)(arow + t * SD + d0)      = packbf2(a0, a1);  // attn half
        *(uint32_t*)(arow + DD + t * SD + d0) = packbf2(h0, h1);  // hyb half
    }
}

// ---------------- fused bf16 mma.sync GEMM + final epilogue ----------------
// CTA tile 128x128, 4 warps (2m x 2n), warp tile 64x64, BK=64, 3-stage cp.async,
// 2 CTAs/SM. Chunk loop restructured as chunk 0 + 21 triples so every stage
// address is a compile-time constant and ptxas schedules across chunks.
__global__ void __launch_bounds__(128, 2) gemm_kernel(const float* __restrict__ x,
                                                      float* __restrict__ out) {
    extern __shared__ __align__(128) char dsm[];

    const int tid  = threadIdx.x;
    const int wid  = tid >> 5;
    const int lane = tid & 31;
    const int nb = blockIdx.x, mbk = blockIdx.y;
    const int m0 = mbk * 128, n0 = nb * 128;
    const int dd0 = nb * 32;

    const uint32_t st0 = smem_u32(dsm);
    const uint32_t st1 = st0 + STAGE_BYTES;
    const uint32_t st2 = st0 + 2 * STAGE_BYTES;

    const int lrow = tid >> 3;       // 0..15
    const int lcol = tid & 7;        // 0..7

    const int wm = wid & 1;          // 2 m-warps
    const int wn = wid >> 1;         // 2 n-warps
    const int mwarp = wm * 64, nwarp = wn * 64;

    const int lrow16 = lane & 15;
    const int lkhalf = (lane >> 4) * 16;

    float acc[4][8][4];
#pragma unroll
    for (int i = 0; i < 4; i++)
#pragma unroll
        for (int j = 0; j < 8; j++)
#pragma unroll
            for (int q = 0; q < 4; q++) acc[i][j][q] = 0.f;

    const __nv_bfloat16* Abase = g_A  + (size_t)(m0 + lrow) * KTOT + lcol * 8;
    const __nv_bfloat16* Bbase = g_Wc + (size_t)(n0 + lrow) * KTOT + lcol * 8;

    auto load_stage = [&](uint32_t st, int chunk) {
        const __nv_bfloat16* Ap = Abase + chunk * BK;
        const __nv_bfloat16* Bp = Bbase + chunk * BK;
#pragma unroll
        for (int j = 0; j < 8; j++) {   // A: 128 rows x 128B, 16-row steps
            int r = lrow + 16 * j;
            cp_async16(st + SW128(r * 128 + lcol * 16), Ap + (size_t)(16 * j) * KTOT);
        }
#pragma unroll
        for (int j = 0; j < 8; j++) {   // B: 128 rows x 128B
            int r = lrow + 16 * j;
            cp_async16(st + 16384 + SW128(r * 128 + lcol * 16), Bp + (size_t)(16 * j) * KTOT);
        }
        cp_commit();
    };

    uint32_t af[2][4][4], bf[2][4][4];

    auto prefetch = [&](uint32_t stA, int ks, int buf) {
        const uint32_t stB = stA + 16384;
        const int kb = ks * 32 + lkhalf;
#pragma unroll
        for (int i = 0; i < 4; i++)
            ldm_x4(af[buf][i], stA + SW128((mwarp + i * 16 + lrow16) * 128 + kb));
#pragma unroll
        for (int j = 0; j < 4; j++)
            ldm_x4(bf[buf][j], stB + SW128((nwarp + j * 16 + lrow16) * 128 + kb));
    };

    // one chunk: MMA on stage sA, issue loads for chunk c+2 into sLoad,
    // then wait+sync+prefetch ks0 of chunk c+1 from sNext.
    auto step = [&](int c, uint32_t sA, uint32_t sLoad, uint32_t sNext) {
        if (c + 2 < NK_CHUNKS) load_stage(sLoad, c + 2);
#pragma unroll
        for (int ks = 0; ks < 4; ks++) {
            const int cur = ks & 1, nxt = cur ^ 1;
            if (ks < 3) prefetch(sA, ks + 1, nxt);
#pragma unroll
            for (int i = 0; i < 4; i++)
#pragma unroll
                for (int j = 0; j < 4; j++) {
                    mma16816(acc[i][j * 2 + 0], af[cur][i], bf[cur][j][0], bf[cur][j][2]);
                    mma16816(acc[i][j * 2 + 1], af[cur][i], bf[cur][j][1], bf[cur][j][3]);
                }
        }
        if (c + 1 < NK_CHUNKS) {
            if (c + 2 < NK_CHUNKS) cp_wait<1>(); else cp_wait<0>();
            __syncthreads();
            prefetch(sNext, 0, 0);
        }
    };

    load_stage(st0, 0);
    load_stage(st1, 1);
    cp_wait<1>();
    __syncthreads();
    prefetch(st0, 0, 0);

    step(0, st0, st2, st1);                  // chunk 0 (stage 0)
    for (int k = 0; k < 21; k++) {           // chunks 1..63 in stage-aligned triples
        const int c = 3 * k;
        step(c + 1, st1, st0, st2);
        step(c + 2, st2, st1, st0);
        step(c + 3, st0, st2, st1);
    }

    // fused epilogue: out = acc + bias~ + residual-mix of x.
    const int erow = lane >> 2;
    const int ecol = (lane & 3) * 2;
    const int tlo = nwarp >> 5;
#pragma unroll
    for (int j = 0; j < 4; j++) {
        const int colT = nwarp + j * 8 + ecol;
        const int dd = dd0 + (colT & 31);
        const float2 bv0 = *(const float2*)(g_bias + n0 + colT);
        const float2 bv1 = *(const float2*)(g_bias + n0 + colT + 32);
        float rw0[4], rw1[4];
#pragma unroll
        for (int s = 0; s < 4; s++) { rw0[s] = g_sm.Rw[s][tlo]; rw1[s] = g_sm.Rw[s][tlo + 1]; }
#pragma unroll
        for (int i = 0; i < 4; i++) {
#pragma unroll
            for (int rr = 0; rr < 2; rr++) {
                const int m = m0 + mwarp + i * 16 + erow + rr * 8;
                const float* xr = x + (size_t)m * DD + dd;
                float2 xv[4];
#pragma unroll
                for (int s = 0; s < 4; s++) xv[s] = __ldg((const float2*)(xr + s * SD));
                float o0 = acc[i][j][rr * 2 + 0] + bv0.x;
                float o1 = acc[i][j][rr * 2 + 1] + bv0.y;
                float p0 = acc[i][j + 4][rr * 2 + 0] + bv1.x;
                float p1 = acc[i][j + 4][rr * 2 + 1] + bv1.y;
#pragma unroll
                for (int s = 0; s < 4; s++) {
                    o0 += rw0[s] * xv[s].x;  o1 += rw0[s] * xv[s].y;
                    p0 += rw1[s] * xv[s].x;  p1 += rw1[s] * xv[s].y;
                }
                float* ob = out + (size_t)m * DD + tlo * SD + dd;
                *(float2*)ob = make_float2(o0, o1);
                *(float2*)(ob + SD) = make_float2(p0, p1);
            }
        }
    }
}

// ---------------- launch ----------------
extern "C" void kernel_launch(void* const* d_in, const int* in_sizes, int n_in,
                              void* d_out, int out_size) {
    const float* x     = (const float*)d_in[0];
    const float* g     = (const float*)d_in[1];
    const float* b     = (const float*)d_in[2];
    const float* Wa    = (const float*)d_in[3];
    const float* ba    = (const float*)d_in[4];
    const float* Wh    = (const float*)d_in[5];
    const float* bh    = (const float*)d_in[6];
    const float* pre_a = (const float*)d_in[7];
    const float* pre_h = (const float*)d_in[8];
    const float* res_a = (const float*)d_in[9];
    const float* post_a= (const float*)d_in[10];
    const float* sc_a  = (const float*)d_in[11];
    const float* res_h = (const float*)d_in[12];
    const float* post_h= (const float*)d_in[13];
    const float* sc_h  = (const float*)d_in[14];
    const float* cm    = (const float*)d_in[15];
    float* out = (float*)d_out;

    cudaFuncSetAttribute(gemm_kernel, cudaFuncAttributeMaxDynamicSharedMemorySize, DYN_SMEM);

    small_kernel<<<1, 256>>>(pre_a, pre_h, res_a, post_a, sc_a,
                             res_h, post_h, sc_h, cm, ba, bh);
    wtrans_kernel<<<dim3(64, 16, 2), dim3(32, 8)>>>(Wa, Wh);
    pre_kernel<<<MROWS, 256>>>(x, g, b);
    gemm_kernel<<<dim3(16, 128), 128, DYN_SMEM>>>(x, out);
}

// round 13
// speedup vs baseline: 1.0521x; 1.0521x over previous
#include <cuda_runtime.h>
#include <cuda_bf16.h>
#include <cstdint>

#define DEV_INLINE __device__ __forceinline__

// ---------------- problem sizes (fixed) ----------------
#define DD    2048
#define SD    512
#define MROWS 16384          // B*N = 4*4096
#define KTOT  4096           // concatenated K (attn 2048 | hyb 2048)
#define BK    64             // K elements per pipeline chunk (bf16)
#define NK_CHUNKS 64         // 4096/64
#define STAGES 3
#define STAGE_BYTES 32768    // A tile 16KB + B tile 16KB
#define DYN_SMEM (STAGES * STAGE_BYTES)

// ---------------- device scratch (static, no allocs) ----------------
__device__ __nv_bfloat16 g_A [(size_t)MROWS * KTOT];  // [m][attn 0..2047 | hyb 2048..4095]
__device__ __nv_bfloat16 g_Wc[(size_t)DD * KTOT];     // permuted combined weights [p][k]
__device__ float         g_bias[DD];                  // permuted combined bias

struct SmallMats {
    float pre_a[4][4], pre_h[4][4];
    float ca_mix[4][4], ch_mix[4][4];   // alpha*sc*post (t,s)
    float Rw[4][4];                     // combined residual mix (s,t)
    float alpha;
};
__device__ SmallMats g_sm;

// ---------------- PTX helpers (base ISA only: sm_80+) ----------------
DEV_INLINE uint32_t smem_u32(const void* p) {
    uint32_t a;
    asm("{ .reg .u64 t; cvta.to.shared.u64 t, %1; cvt.u32.u64 %0, t; }" : "=r"(a) : "l"(p));
    return a;
}
#define SW128(o) ((o) ^ ((((uint32_t)(o)) >> 3) & 0x70u))

DEV_INLINE void cp_async16(uint32_t dst, const void* src) {
    asm volatile("cp.async.cg.shared.global [%0], [%1], 16;" :: "r"(dst), "l"(src));
}
DEV_INLINE void cp_commit() { asm volatile("cp.async.commit_group;" ::: "memory"); }
template<int N> DEV_INLINE void cp_wait() {
    asm volatile("cp.async.wait_group %0;" :: "n"(N) : "memory");
}
DEV_INLINE void ldm_x4(uint32_t* r, uint32_t addr) {
    asm volatile("ldmatrix.sync.aligned.m8n8.x4.shared.b16 {%0,%1,%2,%3}, [%4];"
                 : "=r"(r[0]), "=r"(r[1]), "=r"(r[2]), "=r"(r[3]) : "r"(addr));
}
DEV_INLINE void mma16816(float* d, const uint32_t* a, uint32_t b0, uint32_t b1) {
    asm volatile(
        "mma.sync.aligned.m16n8k16.row.col.f32.bf16.bf16.f32 "
        "{%0,%1,%2,%3}, {%4,%5,%6,%7}, {%8,%9}, {%0,%1,%2,%3};"
        : "+f"(d[0]), "+f"(d[1]), "+f"(d[2]), "+f"(d[3])
        : "r"(a[0]), "r"(a[1]), "r"(a[2]), "r"(a[3]), "r"(b0), "r"(b1));
}

// ---------------- small 4x4 matrices + combined bias (one kernel) ----------------
DEV_INLINE void softmax4(const float* L, float O[4][4]) {
    for (int s = 0; s < 4; s++) {
        float mx = L[s*4];
        for (int t = 1; t < 4; t++) mx = fmaxf(mx, L[s*4+t]);
        float sum = 0.f, e[4];
        for (int t = 0; t < 4; t++) { e[t] = expf(L[s*4+t] - mx); sum += e[t]; }
        float inv = 1.f / sum;
        for (int t = 0; t < 4; t++) O[s][t] = e[t] * inv;
    }
}
DEV_INLINE void sinkhorn4(const float* L, float P[4][4]) {
    float mx = L[0];
    for (int i = 1; i < 16; i++) mx = fmaxf(mx, L[i]);
    for (int s = 0; s < 4; s++)
        for (int t = 0; t < 4; t++) P[s][t] = expf(L[s*4+t] - mx);
    for (int it = 0; it < 20; it++) {
        for (int s = 0; s < 4; s++) {
            float rs = P[s][0] + P[s][1] + P[s][2] + P[s][3];
            float inv = 1.f / (rs + 1e-8f);
            for (int t = 0; t < 4; t++) P[s][t] *= inv;
        }
        for (int t = 0; t < 4; t++) {
            float cs = P[0][t] + P[1][t] + P[2][t] + P[3][t];
            float inv = 1.f / (cs + 1e-8f);
            for (int s = 0; s < 4; s++) P[s][t] *= inv;
        }
    }
}
__global__ void __launch_bounds__(256) small_kernel(
        const float* pa, const float* ph,
        const float* ra, const float* po_a, const float* sa,
        const float* rh, const float* po_h, const float* sh,
        const float* cm, const float* ba, const float* bh) {
    __shared__ SmallMats sm;
    if (threadIdx.x == 0) {
        float post_a[4][4], post_h[4][4], res_a[4][4], res_h[4][4];
        softmax4(pa,   sm.pre_a);
        softmax4(ph,   sm.pre_h);
        softmax4(po_a, post_a);
        softmax4(po_h, post_h);
        sinkhorn4(ra,  res_a);
        sinkhorn4(rh,  res_h);
        float alpha = 1.f / (1.f + expf(-cm[0]));
        sm.alpha = alpha;
        float beta = 1.f - alpha;
        for (int t = 0; t < 4; t++)
            for (int s = 0; s < 4; s++) {
                sm.ca_mix[t][s] = alpha * sa[t] * post_a[t][s];
                sm.ch_mix[t][s] = beta  * sh[t] * post_h[t][s];
                sm.Rw[s][t]     = alpha * res_a[s][t] + beta * res_h[s][t];
            }
        g_sm = sm;
    }
    __syncthreads();
    // combined permuted bias: p = (dd>>5)*128 + t*32 + (dd&31)
    for (int p = threadIdx.x; p < DD; p += 256) {
        int t = (p >> 5) & 3;
        int dd = ((p >> 7) << 5) + (p & 31);
        float v = 0.f;
#pragma unroll
        for (int s = 0; s < 4; s++)
            v += sm.ca_mix[t][s] * ba[s * SD + dd] + sm.ch_mix[t][s] * bh[s * SD + dd];
        g_bias[p] = v;
    }
}

// ---------------- W transpose + post-mix fold + bf16 quantize ----------------
// One block handles (k-block, dd-block, z) and emits ALL 4 t-streams.
__global__ void wtrans_kernel(const float* __restrict__ Wa, const float* __restrict__ Wh) {
    __shared__ float t4[4][32][33];
    const int z = blockIdx.z;
    const float* W = z ? Wh : Wa;
    const int k0  = blockIdx.x * 32;
    const int dd0 = blockIdx.y * 32;
    const int tx = threadIdx.x, ty = threadIdx.y;
#pragma unroll
    for (int s = 0; s < 4; s++)
#pragma unroll
        for (int j = 0; j < 32; j += 8)
            t4[s][ty + j][tx] = W[(size_t)(k0 + ty + j) * DD + s * SD + dd0 + tx];
    __syncthreads();
#pragma unroll
    for (int t = 0; t < 4; t++) {
        float c[4];
#pragma unroll
        for (int s = 0; s < 4; s++)
            c[s] = z ? g_sm.ch_mix[t][s] : g_sm.ca_mix[t][s];
        const size_t prow = (size_t)(blockIdx.y * 128 + t * 32);
#pragma unroll
        for (int j = 0; j < 32; j += 8) {
            int pi = ty + j;
            float v = 0.f;
#pragma unroll
            for (int s = 0; s < 4; s++) v += c[s] * t4[s][tx][pi];
            g_Wc[(prow + pi) * KTOT + z * DD + k0 + tx] = __float2bfloat16(v);
        }
    }
}

// ---------------- fused LayerNorm + H_pre mixes -> bf16 GEMM inputs ----------------
DEV_INLINE uint32_t packbf2(float a, float b) {
    __nv_bfloat162 t = __floats2bfloat162_rn(a, b);
    return *reinterpret_cast<uint32_t*>(&t);
}
__global__ void __launch_bounds__(256) pre_kernel(const float* __restrict__ x,
                                                  const float* __restrict__ gamma,
                                                  const float* __restrict__ beta) {
    __shared__ float sred[18];
    const int tid = threadIdx.x;
    const float* xr = x + (size_t)blockIdx.x * DD;
    const int d0 = tid * 2;

    float2 xv[4];
    float s1 = 0.f, s2 = 0.f;
#pragma unroll
    for (int s = 0; s < 4; s++) {
        xv[s] = *(const float2*)(xr + s * SD + d0);
        s1 += xv[s].x + xv[s].y;
        s2 += xv[s].x * xv[s].x + xv[s].y * xv[s].y;
    }
#pragma unroll
    for (int off = 16; off > 0; off >>= 1) {
        s1 += __shfl_xor_sync(0xffffffffu, s1, off);
        s2 += __shfl_xor_sync(0xffffffffu, s2, off);
    }
    if ((tid & 31) == 0) { sred[tid >> 5] = s1; sred[8 + (tid >> 5)] = s2; }
    __syncthreads();
    if (tid == 0) {
        float a = 0.f, b = 0.f;
        for (int w = 0; w < 8; w++) { a += sred[w]; b += sred[8 + w]; }
        float mu = a * (1.f / DD);
        float var = b * (1.f / DD) - mu * mu;
        sred[16] = mu;
        sred[17] = rsqrtf(var + 1e-5f);
    }
    __syncthreads();
    const float mu = sred[16], rstd = sred[17];

    float n0[4], n1[4];
#pragma unroll
    for (int s = 0; s < 4; s++) {
        float2 gv = __ldg((const float2*)(gamma + s * SD + d0));
        float2 bv = __ldg((const float2*)(beta  + s * SD + d0));
        n0[s] = (xv[s].x - mu) * rstd * gv.x + bv.x;
        n1[s] = (xv[s].y - mu) * rstd * gv.y + bv.y;
    }

    __nv_bfloat16* arow = g_A + (size_t)blockIdx.x * KTOT;
#pragma unroll
    for (int t = 0; t < 4; t++) {
        float a0 = 0.f, a1 = 0.f, h0 = 0.f, h1 = 0.f;
#pragma unroll
        for (int s = 0; s < 4; s++) {
            float wa = g_sm.pre_a[s][t];
            float wh = g_sm.pre_h[s][t];
            a0 += wa * n0[s];  a1 += wa * n1[s];
            h0 += wh * xv[s].x; h1 += wh * xv[s].y;
        }
        *(uint32_t*)(arow + t * SD + d0)      = packbf2(a0, a1);  // attn half
        *(uint32_t*)(arow + DD + t * SD + d0) = packbf2(h0, h1);  // hyb half
    }
}

// ---------------- fused bf16 mma.sync GEMM + final epilogue ----------------
// CTA tile 128x128, 4 warps (2m x 2n), warp tile 64x64, BK=64, 3-stage cp.async,
// 2 CTAs/SM. Rolled chunk loop (dynamic stage indexing — R11 best-known form;
// the stage-specialized unroll blew regs to 255 and regressed).
__global__ void __launch_bounds__(128, 2) gemm_kernel(const float* __restrict__ x,
                                                      float* __restrict__ out) {
    extern __shared__ __align__(128) char dsm[];

    const int tid  = threadIdx.x;
    const int wid  = tid >> 5;
    const int lane = tid & 31;
    const int nb = blockIdx.x, mbk = blockIdx.y;
    const int m0 = mbk * 128, n0 = nb * 128;
    const int dd0 = nb * 32;

    const uint32_t smem_base = smem_u32(dsm);

    const int lrow = tid >> 3;       // 0..15
    const int lcol = tid & 7;        // 0..7

    const int wm = wid & 1;          // 2 m-warps
    const int wn = wid >> 1;         // 2 n-warps
    const int mwarp = wm * 64, nwarp = wn * 64;

    const int lrow16 = lane & 15;
    const int lkhalf = (lane >> 4) * 16;

    float acc[4][8][4];
#pragma unroll
    for (int i = 0; i < 4; i++)
#pragma unroll
        for (int j = 0; j < 8; j++)
#pragma unroll
            for (int q = 0; q < 4; q++) acc[i][j][q] = 0.f;

    const __nv_bfloat16* Abase = g_A  + (size_t)(m0 + lrow) * KTOT + lcol * 8;
    const __nv_bfloat16* Bbase = g_Wc + (size_t)(n0 + lrow) * KTOT + lcol * 8;

    auto load_stage = [&](int stage, int chunk) {
        const uint32_t st = smem_base + stage * STAGE_BYTES;
        const __nv_bfloat16* Ap = Abase + chunk * BK;
        const __nv_bfloat16* Bp = Bbase + chunk * BK;
#pragma unroll
        for (int j = 0; j < 8; j++) {   // A: 128 rows x 128B, 16-row steps
            int r = lrow + 16 * j;
            cp_async16(st + SW128(r * 128 + lcol * 16), Ap + (size_t)(16 * j) * KTOT);
        }
#pragma unroll
        for (int j = 0; j < 8; j++) {   // B: 128 rows x 128B
            int r = lrow + 16 * j;
            cp_async16(st + 16384 + SW128(r * 128 + lcol * 16), Bp + (size_t)(16 * j) * KTOT);
        }
        cp_commit();
    };

    uint32_t af[2][4][4], bf[2][4][4];

    auto prefetch = [&](uint32_t stA, int ks, int buf) {
        const uint32_t stB = stA + 16384;
        const int kb = ks * 32 + lkhalf;
#pragma unroll
        for (int i = 0; i < 4; i++)
            ldm_x4(af[buf][i], stA + SW128((mwarp + i * 16 + lrow16) * 128 + kb));
#pragma unroll
        for (int j = 0; j < 4; j++)
            ldm_x4(bf[buf][j], stB + SW128((nwarp + j * 16 + lrow16) * 128 + kb));
    };

    load_stage(0, 0);
    load_stage(1, 1);

    cp_wait<1>();          // chunk 0 ready
    __syncthreads();
    prefetch(smem_base, 0, 0);   // chunk 0, ks=0

    for (int c = 0; c < NK_CHUNKS; c++) {
        const uint32_t stA = smem_base + (c % STAGES) * STAGE_BYTES;
        if (c + 2 < NK_CHUNKS) load_stage((c + 2) % STAGES, c + 2);

#pragma unroll
        for (int ks = 0; ks < 4; ks++) {
            const int cur = ks & 1, nxt = cur ^ 1;
            if (ks < 3) prefetch(stA, ks + 1, nxt);
#pragma unroll
            for (int i = 0; i < 4; i++)
#pragma unroll
                for (int j = 0; j < 4; j++) {
                    mma16816(acc[i][j * 2 + 0], af[cur][i], bf[cur][j][0], bf[cur][j][2]);
                    mma16816(acc[i][j * 2 + 1], af[cur][i], bf[cur][j][1], bf[cur][j][3]);
                }
        }

        if (c + 1 < NK_CHUNKS) {
            if (c + 2 < NK_CHUNKS) cp_wait<1>(); else cp_wait<0>();
            __syncthreads();     // also guards stage (c)%3 reuse at iter c+1
            prefetch(smem_base + ((c + 1) % STAGES) * STAGE_BYTES, 0, 0);
        }
    }

    // fused epilogue: out = acc + bias~ + residual-mix of x.
    const int erow = lane >> 2;
    const int ecol = (lane & 3) * 2;
    const int tlo = nwarp >> 5;
#pragma unroll
    for (int j = 0; j < 4; j++) {
        const int colT = nwarp + j * 8 + ecol;
        const int dd = dd0 + (colT & 31);
        const float2 bv0 = *(const float2*)(g_bias + n0 + colT);
        const float2 bv1 = *(const float2*)(g_bias + n0 + colT + 32);
        float rw0[4], rw1[4];
#pragma unroll
        for (int s = 0; s < 4; s++) { rw0[s] = g_sm.Rw[s][tlo]; rw1[s] = g_sm.Rw[s][tlo + 1]; }
#pragma unroll
        for (int i = 0; i < 4; i++) {
#pragma unroll
            for (int rr = 0; rr < 2; rr++) {
                const int m = m0 + mwarp + i * 16 + erow + rr * 8;
                const float* xr = x + (size_t)m * DD + dd;
                float2 xv[4];
#pragma unroll
                for (int s = 0; s < 4; s++) xv[s] = __ldg((const float2*)(xr + s * SD));
                float o0 = acc[i][j][rr * 2 + 0] + bv0.x;
                float o1 = acc[i][j][rr * 2 + 1] + bv0.y;
                float p0 = acc[i][j + 4][rr * 2 + 0] + bv1.x;
                float p1 = acc[i][j + 4][rr * 2 + 1] + bv1.y;
#pragma unroll
                for (int s = 0; s < 4; s++) {
                    o0 += rw0[s] * xv[s].x;  o1 += rw0[s] * xv[s].y;
                    p0 += rw1[s] * xv[s].x;  p1 += rw1[s] * xv[s].y;
                }
                float* ob = out + (size_t)m * DD + tlo * SD + dd;
                *(float2*)ob = make_float2(o0, o1);
                *(float2*)(ob + SD) = make_float2(p0, p1);
            }
        }
    }
}

// ---------------- launch ----------------
extern "C" void kernel_launch(void* const* d_in, const int* in_sizes, int n_in,
                              void* d_out, int out_size) {
    const float* x     = (const float*)d_in[0];
    const float* g     = (const float*)d_in[1];
    const float* b     = (const float*)d_in[2];
    const float* Wa    = (const float*)d_in[3];
    const float* ba    = (const float*)d_in[4];
    const float* Wh    = (const float*)d_in[5];
    const float* bh    = (const float*)d_in[6];
    const float* pre_a = (const float*)d_in[7];
    const float* pre_h = (const float*)d_in[8];
    const float* res_a = (const float*)d_in[9];
    const float* post_a= (const float*)d_in[10];
    const float* sc_a  = (const float*)d_in[11];
    const float* res_h = (const float*)d_in[12];
    const float* post_h= (const float*)d_in[13];
    const float* sc_h  = (const float*)d_in[14];
    const float* cm    = (const float*)d_in[15];
    float* out = (float*)d_out;

    cudaFuncSetAttribute(gemm_kernel, cudaFuncAttributeMaxDynamicSharedMemorySize, DYN_SMEM);

    small_kernel<<<1, 256>>>(pre_a, pre_h, res_a, post_a, sc_a,
                             res_h, post_h, sc_h, cm, ba, bh);
    wtrans_kernel<<<dim3(64, 16, 2), dim3(32, 8)>>>(Wa, Wh);
    pre_kernel<<<MROWS, 256>>>(x, g, b);
    gemm_kernel<<<dim3(16, 128), 128, DYN_SMEM>>>(x, out);
}

// round 14
// speedup vs baseline: 1.0581x; 1.0057x over previous
#include <cuda_runtime.h>
#include <cuda_bf16.h>
#include <cstdint>

#define DEV_INLINE __device__ __forceinline__

// ---------------- problem sizes (fixed) ----------------
#define DD    2048
#define SD    512
#define MROWS 16384          // B*N = 4*4096
#define KTOT  4096           // concatenated K (attn 2048 | hyb 2048)
#define BK    64             // K elements per pipeline chunk (bf16)
#define NK_CHUNKS 64         // 4096/64
#define STAGES 3
#define STAGE_BYTES 32768    // A tile 16KB + B tile 16KB
#define DYN_SMEM (STAGES * STAGE_BYTES)
#define WT_BLOCKS 2048       // 64 kblk * 16 ddblk * 2 z

// ---------------- device scratch (static, no allocs) ----------------
__device__ __nv_bfloat16 g_A [(size_t)MROWS * KTOT];  // [m][attn 0..2047 | hyb 2048..4095]
__device__ __nv_bfloat16 g_Wc[(size_t)DD * KTOT];     // permuted combined weights [p][k]
__device__ float         g_bias[DD];                  // permuted combined bias

struct SmallMats {
    float pre_a[4][4], pre_h[4][4];
    float ca_mix[4][4], ch_mix[4][4];   // alpha*sc*post (t,s)
    float Rw[4][4];                     // combined residual mix (s,t)
    float alpha;
};
__device__ SmallMats g_sm;

// ---------------- PTX helpers (base ISA only: sm_80+) ----------------
DEV_INLINE uint32_t smem_u32(const void* p) {
    uint32_t a;
    asm("{ .reg .u64 t; cvta.to.shared.u64 t, %1; cvt.u32.u64 %0, t; }" : "=r"(a) : "l"(p));
    return a;
}
#define SW128(o) ((o) ^ ((((uint32_t)(o)) >> 3) & 0x70u))

DEV_INLINE void cp_async16(uint32_t dst, const void* src) {
    asm volatile("cp.async.cg.shared.global [%0], [%1], 16;" :: "r"(dst), "l"(src));
}
DEV_INLINE void cp_commit() { asm volatile("cp.async.commit_group;" ::: "memory"); }
template<int N> DEV_INLINE void cp_wait() {
    asm volatile("cp.async.wait_group %0;" :: "n"(N) : "memory");
}
DEV_INLINE void ldm_x4(uint32_t* r, uint32_t addr) {
    asm volatile("ldmatrix.sync.aligned.m8n8.x4.shared.b16 {%0,%1,%2,%3}, [%4];"
                 : "=r"(r[0]), "=r"(r[1]), "=r"(r[2]), "=r"(r[3]) : "r"(addr));
}
DEV_INLINE void mma16816(float* d, const uint32_t* a, uint32_t b0, uint32_t b1) {
    asm volatile(
        "mma.sync.aligned.m16n8k16.row.col.f32.bf16.bf16.f32 "
        "{%0,%1,%2,%3}, {%4,%5,%6,%7}, {%8,%9}, {%0,%1,%2,%3};"
        : "+f"(d[0]), "+f"(d[1]), "+f"(d[2]), "+f"(d[3])
        : "r"(a[0]), "r"(a[1]), "r"(a[2]), "r"(a[3]), "r"(b0), "r"(b1));
}

// ---------------- small 4x4 matrices + combined bias (one kernel) ----------------
DEV_INLINE void softmax4(const float* L, float O[4][4]) {
    for (int s = 0; s < 4; s++) {
        float mx = L[s*4];
        for (int t = 1; t < 4; t++) mx = fmaxf(mx, L[s*4+t]);
        float sum = 0.f, e[4];
        for (int t = 0; t < 4; t++) { e[t] = expf(L[s*4+t] - mx); sum += e[t]; }
        float inv = 1.f / sum;
        for (int t = 0; t < 4; t++) O[s][t] = e[t] * inv;
    }
}
DEV_INLINE void sinkhorn4(const float* L, float P[4][4]) {
    float mx = L[0];
    for (int i = 1; i < 16; i++) mx = fmaxf(mx, L[i]);
    for (int s = 0; s < 4; s++)
        for (int t = 0; t < 4; t++) P[s][t] = expf(L[s*4+t] - mx);
    for (int it = 0; it < 20; it++) {
        for (int s = 0; s < 4; s++) {
            float rs = P[s][0] + P[s][1] + P[s][2] + P[s][3];
            float inv = 1.f / (rs + 1e-8f);
            for (int t = 0; t < 4; t++) P[s][t] *= inv;
        }
        for (int t = 0; t < 4; t++) {
            float cs = P[0][t] + P[1][t] + P[2][t] + P[3][t];
            float inv = 1.f / (cs + 1e-8f);
            for (int s = 0; s < 4; s++) P[s][t] *= inv;
        }
    }
}
__global__ void __launch_bounds__(256) small_kernel(
        const float* pa, const float* ph,
        const float* ra, const float* po_a, const float* sa,
        const float* rh, const float* po_h, const float* sh,
        const float* cm, const float* ba, const float* bh) {
    __shared__ SmallMats sm;
    if (threadIdx.x == 0) {
        float post_a[4][4], post_h[4][4], res_a[4][4], res_h[4][4];
        softmax4(pa,   sm.pre_a);
        softmax4(ph,   sm.pre_h);
        softmax4(po_a, post_a);
        softmax4(po_h, post_h);
        sinkhorn4(ra,  res_a);
        sinkhorn4(rh,  res_h);
        float alpha = 1.f / (1.f + expf(-cm[0]));
        sm.alpha = alpha;
        float beta = 1.f - alpha;
        for (int t = 0; t < 4; t++)
            for (int s = 0; s < 4; s++) {
                sm.ca_mix[t][s] = alpha * sa[t] * post_a[t][s];
                sm.ch_mix[t][s] = beta  * sh[t] * post_h[t][s];
                sm.Rw[s][t]     = alpha * res_a[s][t] + beta * res_h[s][t];
            }
        g_sm = sm;
    }
    __syncthreads();
    // combined permuted bias: p = (dd>>5)*128 + t*32 + (dd&31)
    for (int p = threadIdx.x; p < DD; p += 256) {
        int t = (p >> 5) & 3;
        int dd = ((p >> 7) << 5) + (p & 31);
        float v = 0.f;
#pragma unroll
        for (int s = 0; s < 4; s++)
            v += sm.ca_mix[t][s] * ba[s * SD + dd] + sm.ch_mix[t][s] * bh[s * SD + dd];
        g_bias[p] = v;
    }
}

// ---------------- fused prep: LayerNorm+H_pre rows AND W transform blocks ----------
// blockIdx.x <  MROWS      : one x row -> bf16 GEMM A row (attn|hyb)
// blockIdx.x >= MROWS      : one (kblk, ddblk, z) W tile -> g_Wc (all 4 t-streams)
// Fusing lets the W transform's ~12us of traffic overlap the LN wave.
DEV_INLINE uint32_t packbf2(float a, float b) {
    __nv_bfloat162 t = __floats2bfloat162_rn(a, b);
    return *reinterpret_cast<uint32_t*>(&t);
}
__global__ void __launch_bounds__(256) prep_kernel(const float* __restrict__ x,
                                                   const float* __restrict__ gamma,
                                                   const float* __restrict__ beta,
                                                   const float* __restrict__ Wa,
                                                   const float* __restrict__ Wh) {
    if (blockIdx.x >= MROWS) {
        // ---- W transform block ----
        __shared__ float t4[4][32][33];
        const int w = blockIdx.x - MROWS;
        const int kblk = w & 63;
        const int ddblk = (w >> 6) & 15;
        const int z = w >> 10;
        const float* W = z ? Wh : Wa;
        const int k0  = kblk * 32;
        const int dd0 = ddblk * 32;
        const int tx = threadIdx.x & 31, ty = threadIdx.x >> 5;   // 32x8
#pragma unroll
        for (int s = 0; s < 4; s++)
#pragma unroll
            for (int j = 0; j < 32; j += 8)
                t4[s][ty + j][tx] = W[(size_t)(k0 + ty + j) * DD + s * SD + dd0 + tx];
        __syncthreads();
#pragma unroll
        for (int t = 0; t < 4; t++) {
            float c[4];
#pragma unroll
            for (int s = 0; s < 4; s++)
                c[s] = z ? g_sm.ch_mix[t][s] : g_sm.ca_mix[t][s];
            const size_t prow = (size_t)(ddblk * 128 + t * 32);
#pragma unroll
            for (int j = 0; j < 32; j += 8) {
                int pi = ty + j;
                float v = 0.f;
#pragma unroll
                for (int s = 0; s < 4; s++) v += c[s] * t4[s][tx][pi];
                g_Wc[(prow + pi) * KTOT + z * DD + k0 + tx] = __float2bfloat16(v);
            }
        }
        return;
    }

    // ---- LayerNorm + H_pre row ----
    __shared__ float sred[18];
    const int tid = threadIdx.x;
    const float* xr = x + (size_t)blockIdx.x * DD;
    const int d0 = tid * 2;

    float2 xv[4];
    float s1 = 0.f, s2 = 0.f;
#pragma unroll
    for (int s = 0; s < 4; s++) {
        xv[s] = *(const float2*)(xr + s * SD + d0);
        s1 += xv[s].x + xv[s].y;
        s2 += xv[s].x * xv[s].x + xv[s].y * xv[s].y;
    }
#pragma unroll
    for (int off = 16; off > 0; off >>= 1) {
        s1 += __shfl_xor_sync(0xffffffffu, s1, off);
        s2 += __shfl_xor_sync(0xffffffffu, s2, off);
    }
    if ((tid & 31) == 0) { sred[tid >> 5] = s1; sred[8 + (tid >> 5)] = s2; }
    __syncthreads();
    if (tid == 0) {
        float a = 0.f, b = 0.f;
        for (int w = 0; w < 8; w++) { a += sred[w]; b += sred[8 + w]; }
        float mu = a * (1.f / DD);
        float var = b * (1.f / DD) - mu * mu;
        sred[16] = mu;
        sred[17] = rsqrtf(var + 1e-5f);
    }
    __syncthreads();
    const float mu = sred[16], rstd = sred[17];

    float n0[4], n1[4];
#pragma unroll
    for (int s = 0; s < 4; s++) {
        float2 gv = __ldg((const float2*)(gamma + s * SD + d0));
        float2 bv = __ldg((const float2*)(beta  + s * SD + d0));
        n0[s] = (xv[s].x - mu) * rstd * gv.x + bv.x;
        n1[s] = (xv[s].y - mu) * rstd * gv.y + bv.y;
    }

    __nv_bfloat16* arow = g_A + (size_t)blockIdx.x * KTOT;
#pragma unroll
    for (int t = 0; t < 4; t++) {
        float a0 = 0.f, a1 = 0.f, h0 = 0.f, h1 = 0.f;
#pragma unroll
        for (int s = 0; s < 4; s++) {
            float wa = g_sm.pre_a[s][t];
            float wh = g_sm.pre_h[s][t];
            a0 += wa * n0[s];  a1 += wa * n1[s];
            h0 += wh * xv[s].x; h1 += wh * xv[s].y;
        }
        *(uint32_t*)(arow + t * SD + d0)      = packbf2(a0, a1);  // attn half
        *(uint32_t*)(arow + DD + t * SD + d0) = packbf2(h0, h1);  // hyb half
    }
}

// ---------------- fused bf16 mma.sync GEMM + final epilogue ----------------
// CTA tile 128x128, 4 warps (2m x 2n), warp tile 64x64, BK=64, 3-stage cp.async,
// 2 CTAs/SM. Rolled chunk loop; stage addressing via register rotation (no %3).
__global__ void __launch_bounds__(128, 2) gemm_kernel(const float* __restrict__ x,
                                                      float* __restrict__ out) {
    extern __shared__ __align__(128) char dsm[];

    const int tid  = threadIdx.x;
    const int wid  = tid >> 5;
    const int lane = tid & 31;
    const int nb = blockIdx.x, mbk = blockIdx.y;
    const int m0 = mbk * 128, n0 = nb * 128;
    const int dd0 = nb * 32;

    const uint32_t smem_base = smem_u32(dsm);

    const int lrow = tid >> 3;       // 0..15
    const int lcol = tid & 7;        // 0..7

    const int wm = wid & 1;          // 2 m-warps
    const int wn = wid >> 1;         // 2 n-warps
    const int mwarp = wm * 64, nwarp = wn * 64;

    const int lrow16 = lane & 15;
    const int lkhalf = (lane >> 4) * 16;

    float acc[4][8][4];
#pragma unroll
    for (int i = 0; i < 4; i++)
#pragma unroll
        for (int j = 0; j < 8; j++)
#pragma unroll
            for (int q = 0; q < 4; q++) acc[i][j][q] = 0.f;

    const __nv_bfloat16* Abase = g_A  + (size_t)(m0 + lrow) * KTOT + lcol * 8;
    const __nv_bfloat16* Bbase = g_Wc + (size_t)(n0 + lrow) * KTOT + lcol * 8;

    auto load_stage = [&](uint32_t st, int chunk) {
        const __nv_bfloat16* Ap = Abase + chunk * BK;
        const __nv_bfloat16* Bp = Bbase + chunk * BK;
#pragma unroll
        for (int j = 0; j < 8; j++) {   // A: 128 rows x 128B, 16-row steps
            int r = lrow + 16 * j;
            cp_async16(st + SW128(r * 128 + lcol * 16), Ap + (size_t)(16 * j) * KTOT);
        }
#pragma unroll
        for (int j = 0; j < 8; j++) {   // B: 128 rows x 128B
            int r = lrow + 16 * j;
            cp_async16(st + 16384 + SW128(r * 128 + lcol * 16), Bp + (size_t)(16 * j) * KTOT);
        }
        cp_commit();
    };

    uint32_t af[2][4][4], bf[2][4][4];

    auto prefetch = [&](uint32_t stA, int ks, int buf) {
        const uint32_t stB = stA + 16384;
        const int kb = ks * 32 + lkhalf;
#pragma unroll
        for (int i = 0; i < 4; i++)
            ldm_x4(af[buf][i], stA + SW128((mwarp + i * 16 + lrow16) * 128 + kb));
#pragma unroll
        for (int j = 0; j < 4; j++)
            ldm_x4(bf[buf][j], stB + SW128((nwarp + j * 16 + lrow16) * 128 + kb));
    };

    // rotating stage pointers: sCur = MMA stage, sNext = next chunk's stage,
    // sLoad = stage receiving chunk c+2's cp.async
    uint32_t sCur  = smem_base;
    uint32_t sNext = smem_base + STAGE_BYTES;
    uint32_t sLoad = smem_base + 2 * STAGE_BYTES;

    load_stage(sCur, 0);
    load_stage(sNext, 1);

    cp_wait<1>();          // chunk 0 ready
    __syncthreads();
    prefetch(sCur, 0, 0);  // chunk 0, ks=0

    for (int c = 0; c < NK_CHUNKS; c++) {
        if (c + 2 < NK_CHUNKS) load_stage(sLoad, c + 2);

#pragma unroll
        for (int ks = 0; ks < 4; ks++) {
            const int cur = ks & 1, nxt = cur ^ 1;
            if (ks < 3) prefetch(sCur, ks + 1, nxt);
#pragma unroll
            for (int i = 0; i < 4; i++)
#pragma unroll
                for (int j = 0; j < 4; j++) {
                    mma16816(acc[i][j * 2 + 0], af[cur][i], bf[cur][j][0], bf[cur][j][2]);
                    mma16816(acc[i][j * 2 + 1], af[cur][i], bf[cur][j][1], bf[cur][j][3]);
                }
        }

        if (c + 1 < NK_CHUNKS) {
            if (c + 2 < NK_CHUNKS) cp_wait<1>(); else cp_wait<0>();
            __syncthreads();     // also guards sCur reuse as next sLoad
            prefetch(sNext, 0, 0);
        }
        uint32_t t = sCur; sCur = sNext; sNext = sLoad; sLoad = t;
    }

    // fused epilogue: out = acc + bias~ + residual-mix of x.
    const int erow = lane >> 2;
    const int ecol = (lane & 3) * 2;
    const int tlo = nwarp >> 5;
#pragma unroll
    for (int j = 0; j < 4; j++) {
        const int colT = nwarp + j * 8 + ecol;
        const int dd = dd0 + (colT & 31);
        const float2 bv0 = *(const float2*)(g_bias + n0 + colT);
        const float2 bv1 = *(const float2*)(g_bias + n0 + colT + 32);
        float rw0[4], rw1[4];
#pragma unroll
        for (int s = 0; s < 4; s++) { rw0[s] = g_sm.Rw[s][tlo]; rw1[s] = g_sm.Rw[s][tlo + 1]; }
#pragma unroll
        for (int i = 0; i < 4; i++) {
#pragma unroll
            for (int rr = 0; rr < 2; rr++) {
                const int m = m0 + mwarp + i * 16 + erow + rr * 8;
                const float* xr = x + (size_t)m * DD + dd;
                float2 xv[4];
#pragma unroll
                for (int s = 0; s < 4; s++) xv[s] = __ldg((const float2*)(xr + s * SD));
                float o0 = acc[i][j][rr * 2 + 0] + bv0.x;
                float o1 = acc[i][j][rr * 2 + 1] + bv0.y;
                float p0 = acc[i][j + 4][rr * 2 + 0] + bv1.x;
                float p1 = acc[i][j + 4][rr * 2 + 1] + bv1.y;
#pragma unroll
                for (int s = 0; s < 4; s++) {
                    o0 += rw0[s] * xv[s].x;  o1 += rw0[s] * xv[s].y;
                    p0 += rw1[s] * xv[s].x;  p1 += rw1[s] * xv[s].y;
                }
                float* ob = out + (size_t)m * DD + tlo * SD + dd;
                *(float2*)ob = make_float2(o0, o1);
                *(float2*)(ob + SD) = make_float2(p0, p1);
            }
        }
    }
}

// ---------------- launch ----------------
extern "C" void kernel_launch(void* const* d_in, const int* in_sizes, int n_in,
                              void* d_out, int out_size) {
    const float* x     = (const float*)d_in[0];
    const float* g     = (const float*)d_in[1];
    const float* b     = (const float*)d_in[2];
    const float* Wa    = (const float*)d_in[3];
    const float* ba    = (const float*)d_in[4];
    const float* Wh    = (const float*)d_in[5];
    const float* bh    = (const float*)d_in[6];
    const float* pre_a = (const float*)d_in[7];
    const float* pre_h = (const float*)d_in[8];
    const float* res_a = (const float*)d_in[9];
    const float* post_a= (const float*)d_in[10];
    const float* sc_a  = (const float*)d_in[11];
    const float* res_h = (const float*)d_in[12];
    const float* post_h= (const float*)d_in[13];
    const float* sc_h  = (const float*)d_in[14];
    const float* cm    = (const float*)d_in[15];
    float* out = (float*)d_out;

    cudaFuncSetAttribute(gemm_kernel, cudaFuncAttributeMaxDynamicSharedMemorySize, DYN_SMEM);

    small_kernel<<<1, 256>>>(pre_a, pre_h, res_a, post_a, sc_a,
                             res_h, post_h, sc_h, cm, ba, bh);
    prep_kernel<<<MROWS + WT_BLOCKS, 256>>>(x, g, b, Wa, Wh);
    gemm_kernel<<<dim3(16, 128), 128, DYN_SMEM>>>(x, out);
}

// round 16
// speedup vs baseline: 1.0868x; 1.0271x over previous
#include <cuda_runtime.h>
#include <cuda_bf16.h>
#include <cstdint>

#define DEV_INLINE __device__ __forceinline__

// ---------------- problem sizes (fixed) ----------------
#define DD    2048
#define SD    512
#define MROWS 16384          // B*N = 4*4096
#define KTOT  4096           // concatenated K (attn 2048 | hyb 2048)
#define BK    64             // K elements per pipeline chunk (bf16)
#define NK_CHUNKS 64         // 4096/64
#define STAGES 3
#define STAGE_BYTES 32768    // A tile 16KB + B tile 16KB
#define DYN_SMEM (STAGES * STAGE_BYTES)
#define WT_BLOCKS 2048       // 64 kblk * 16 ddblk * 2 z

// ---------------- device scratch (static, no allocs) ----------------
__device__ __nv_bfloat16 g_A [(size_t)MROWS * KTOT];  // [m][attn 0..2047 | hyb 2048..4095]
__device__ __nv_bfloat16 g_Wc[(size_t)DD * KTOT];     // permuted combined weights [p][k]
__device__ float         g_bias[DD];                  // permuted combined bias

struct SmallMats {
    float pre_a[4][4], pre_h[4][4];
    float ca_mix[4][4], ch_mix[4][4];   // alpha*sc*post (t,s)
    float Rw[4][4];                     // combined residual mix (s,t)
    float alpha;
};
__device__ SmallMats g_sm;

// ---------------- PTX helpers (base ISA only: sm_80+) ----------------
DEV_INLINE uint32_t smem_u32(const void* p) {
    uint32_t a;
    asm("{ .reg .u64 t; cvta.to.shared.u64 t, %1; cvt.u32.u64 %0, t; }" : "=r"(a) : "l"(p));
    return a;
}
#define SW128(o) ((o) ^ ((((uint32_t)(o)) >> 3) & 0x70u))

DEV_INLINE void cp_async16(uint32_t dst, const void* src) {
    asm volatile("cp.async.cg.shared.global [%0], [%1], 16;" :: "r"(dst), "l"(src));
}
DEV_INLINE void cp_commit() { asm volatile("cp.async.commit_group;" ::: "memory"); }
template<int N> DEV_INLINE void cp_wait() {
    asm volatile("cp.async.wait_group %0;" :: "n"(N) : "memory");
}
DEV_INLINE void ldm_x4(uint32_t* r, uint32_t addr) {
    asm volatile("ldmatrix.sync.aligned.m8n8.x4.shared.b16 {%0,%1,%2,%3}, [%4];"
                 : "=r"(r[0]), "=r"(r[1]), "=r"(r[2]), "=r"(r[3]) : "r"(addr));
}
DEV_INLINE void mma16816(float* d, const uint32_t* a, uint32_t b0, uint32_t b1) {
    asm volatile(
        "mma.sync.aligned.m16n8k16.row.col.f32.bf16.bf16.f32 "
        "{%0,%1,%2,%3}, {%4,%5,%6,%7}, {%8,%9}, {%0,%1,%2,%3};"
        : "+f"(d[0]), "+f"(d[1]), "+f"(d[2]), "+f"(d[3])
        : "r"(a[0]), "r"(a[1]), "r"(a[2]), "r"(a[3]), "r"(b0), "r"(b1));
}

// ---------------- warp-parallel 4x4 matrix math ----------------
// ALL 32 lanes execute (lanes 16..31 mirror 0..15); xor strides 1/2/4/8 never
// cross the 16-lane halves, so the mirrored copy is self-consistent.
DEV_INLINE float softmax16(float v) {
    float mx = v;
    mx = fmaxf(mx, __shfl_xor_sync(0xffffffffu, mx, 1));
    mx = fmaxf(mx, __shfl_xor_sync(0xffffffffu, mx, 2));
    float e = expf(v - mx);
    float sum = e;
    sum += __shfl_xor_sync(0xffffffffu, sum, 1);
    sum += __shfl_xor_sync(0xffffffffu, sum, 2);
    return e / sum;
}
DEV_INLINE float sinkhorn16(float v) {
    float mx = v;
    mx = fmaxf(mx, __shfl_xor_sync(0xffffffffu, mx, 1));
    mx = fmaxf(mx, __shfl_xor_sync(0xffffffffu, mx, 2));
    mx = fmaxf(mx, __shfl_xor_sync(0xffffffffu, mx, 4));
    mx = fmaxf(mx, __shfl_xor_sync(0xffffffffu, mx, 8));
    float p = expf(v - mx);
#pragma unroll
    for (int it = 0; it < 20; it++) {
        float rs = p;
        rs += __shfl_xor_sync(0xffffffffu, rs, 1);
        rs += __shfl_xor_sync(0xffffffffu, rs, 2);
        p *= 1.f / (rs + 1e-8f);
        float cs = p;
        cs += __shfl_xor_sync(0xffffffffu, cs, 4);
        cs += __shfl_xor_sync(0xffffffffu, cs, 8);
        p *= 1.f / (cs + 1e-8f);
    }
    return p;
}

__global__ void __launch_bounds__(256) small_kernel(
        const float* pa, const float* ph,
        const float* ra, const float* po_a, const float* sa,
        const float* rh, const float* po_h, const float* sh,
        const float* cm, const float* ba, const float* bh) {
    __shared__ float m_pre_a[16], m_pre_h[16], m_res_a[16], m_res_h[16];
    __shared__ float s_ca[16], s_ch[16];   // ca_mix/ch_mix as [t*4+s]
    const int tid = threadIdx.x;
    const int w = tid >> 5, lane = tid & 31;
    const int e = lane & 15;               // element index (mirrored for lane>=16)

    if (w == 0) {
        float r = sinkhorn16(ra[e]);               // e = s*4+t
        if (lane < 16) m_res_a[e] = r;
    } else if (w == 1) {
        float r = sinkhorn16(rh[e]);
        if (lane < 16) m_res_h[e] = r;
    } else if (w == 2) {
        float r = softmax16(pa[e]);
        if (lane < 16) m_pre_a[e] = r;
    } else if (w == 3) {
        float r = softmax16(ph[e]);
        if (lane < 16) m_pre_h[e] = r;
    } else if (w == 4) {                           // e = t*4+s
        float sm = softmax16(po_a[e]);
        float alpha = 1.f / (1.f + expf(-cm[0]));
        if (lane < 16) s_ca[e] = alpha * sa[e >> 2] * sm;
    } else if (w == 5) {
        float sm = softmax16(po_h[e]);
        float beta = 1.f - 1.f / (1.f + expf(-cm[0]));
        if (lane < 16) s_ch[e] = beta * sh[e >> 2] * sm;
    }
    __syncthreads();

    if (tid < 16) {                         // tid = s*4+t
        const int s = tid >> 2, t = tid & 3;
        float alpha = 1.f / (1.f + expf(-cm[0]));
        float beta  = 1.f - alpha;
        g_sm.pre_a[s][t] = m_pre_a[tid];
        g_sm.pre_h[s][t] = m_pre_h[tid];
        g_sm.ca_mix[s][t] = s_ca[tid];      // ca_mix[t'][s'] stored at [t'*4+s']
        g_sm.ch_mix[s][t] = s_ch[tid];
        g_sm.Rw[s][t] = alpha * m_res_a[tid] + beta * m_res_h[tid];
        if (tid == 0) g_sm.alpha = alpha;
    }
    __syncthreads();

    // combined permuted bias: p = (dd>>5)*128 + t*32 + (dd&31)
    for (int p = tid; p < DD; p += 256) {
        int t = (p >> 5) & 3;
        int dd = ((p >> 7) << 5) + (p & 31);
        float v = 0.f;
#pragma unroll
        for (int s = 0; s < 4; s++)
            v += s_ca[t * 4 + s] * ba[s * SD + dd] + s_ch[t * 4 + s] * bh[s * SD + dd];
        g_bias[p] = v;
    }
}

// ---------------- fused prep: LayerNorm+H_pre rows AND W transform blocks ----------
DEV_INLINE uint32_t packbf2(float a, float b) {
    __nv_bfloat162 t = __floats2bfloat162_rn(a, b);
    return *reinterpret_cast<uint32_t*>(&t);
}
__global__ void __launch_bounds__(256) prep_kernel(const float* __restrict__ x,
                                                   const float* __restrict__ gamma,
                                                   const float* __restrict__ beta,
                                                   const float* __restrict__ Wa,
                                                   const float* __restrict__ Wh) {
    if (blockIdx.x >= MROWS) {
        // ---- W transform block ----
        __shared__ float t4[4][32][33];
        const int w = blockIdx.x - MROWS;
        const int kblk = w & 63;
        const int ddblk = (w >> 6) & 15;
        const int z = w >> 10;
        const float* W = z ? Wh : Wa;
        const int k0  = kblk * 32;
        const int dd0 = ddblk * 32;
        const int tx = threadIdx.x & 31, ty = threadIdx.x >> 5;   // 32x8
#pragma unroll
        for (int s = 0; s < 4; s++)
#pragma unroll
            for (int j = 0; j < 32; j += 8)
                t4[s][ty + j][tx] = W[(size_t)(k0 + ty + j) * DD + s * SD + dd0 + tx];
        __syncthreads();
#pragma unroll
        for (int t = 0; t < 4; t++) {
            float c[4];
#pragma unroll
            for (int s = 0; s < 4; s++)
                c[s] = z ? g_sm.ch_mix[t][s] : g_sm.ca_mix[t][s];
            const size_t prow = (size_t)(ddblk * 128 + t * 32);
#pragma unroll
            for (int j = 0; j < 32; j += 8) {
                int pi = ty + j;
                float v = 0.f;
#pragma unroll
                for (int s = 0; s < 4; s++) v += c[s] * t4[s][tx][pi];
                g_Wc[(prow + pi) * KTOT + z * DD + k0 + tx] = __float2bfloat16(v);
            }
        }
        return;
    }

    // ---- LayerNorm + H_pre row ----
    __shared__ float sred[18];
    const int tid = threadIdx.x;
    const float* xr = x + (size_t)blockIdx.x * DD;
    const int d0 = tid * 2;

    float2 xv[4];
    float s1 = 0.f, s2 = 0.f;
#pragma unroll
    for (int s = 0; s < 4; s++) {
        xv[s] = *(const float2*)(xr + s * SD + d0);
        s1 += xv[s].x + xv[s].y;
        s2 += xv[s].x * xv[s].x + xv[s].y * xv[s].y;
    }
#pragma unroll
    for (int off = 16; off > 0; off >>= 1) {
        s1 += __shfl_xor_sync(0xffffffffu, s1, off);
        s2 += __shfl_xor_sync(0xffffffffu, s2, off);
    }
    if ((tid & 31) == 0) { sred[tid >> 5] = s1; sred[8 + (tid >> 5)] = s2; }
    __syncthreads();
    if (tid == 0) {
        float a = 0.f, b = 0.f;
        for (int w = 0; w < 8; w++) { a += sred[w]; b += sred[8 + w]; }
        float mu = a * (1.f / DD);
        float var = b * (1.f / DD) - mu * mu;
        sred[16] = mu;
        sred[17] = rsqrtf(var + 1e-5f);
    }
    __syncthreads();
    const float mu = sred[16], rstd = sred[17];

    float n0[4], n1[4];
#pragma unroll
    for (int s = 0; s < 4; s++) {
        float2 gv = __ldg((const float2*)(gamma + s * SD + d0));
        float2 bv = __ldg((const float2*)(beta  + s * SD + d0));
        n0[s] = (xv[s].x - mu) * rstd * gv.x + bv.x;
        n1[s] = (xv[s].y - mu) * rstd * gv.y + bv.y;
    }

    __nv_bfloat16* arow = g_A + (size_t)blockIdx.x * KTOT;
#pragma unroll
    for (int t = 0; t < 4; t++) {
        float a0 = 0.f, a1 = 0.f, h0 = 0.f, h1 = 0.f;
#pragma unroll
        for (int s = 0; s < 4; s++) {
            float wa = g_sm.pre_a[s][t];
            float wh = g_sm.pre_h[s][t];
            a0 += wa * n0[s];  a1 += wa * n1[s];
            h0 += wh * xv[s].x; h1 += wh * xv[s].y;
        }
        *(uint32_t*)(arow + t * SD + d0)      = packbf2(a0, a1);  // attn half
        *(uint32_t*)(arow + DD + t * SD + d0) = packbf2(h0, h1);  // hyb half
    }
}

// ---------------- fused bf16 mma.sync GEMM + final epilogue ----------------
// CTA tile 128x128, 4 warps (2m x 2n), warp tile 64x64, BK=64, 3-stage cp.async,
// 2 CTAs/SM. Rolled chunk loop; stage addressing via register rotation (no %3).
__global__ void __launch_bounds__(128, 2) gemm_kernel(const float* __restrict__ x,
                                                      float* __restrict__ out) {
    extern __shared__ __align__(128) char dsm[];

    const int tid  = threadIdx.x;
    const int wid  = tid >> 5;
    const int lane = tid & 31;
    const int nb = blockIdx.x, mbk = blockIdx.y;
    const int m0 = mbk * 128, n0 = nb * 128;
    const int dd0 = nb * 32;

    const uint32_t smem_base = smem_u32(dsm);

    const int lrow = tid >> 3;       // 0..15
    const int lcol = tid & 7;        // 0..7

    const int wm = wid & 1;          // 2 m-warps
    const int wn = wid >> 1;         // 2 n-warps
    const int mwarp = wm * 64, nwarp = wn * 64;

    const int lrow16 = lane & 15;
    const int lkhalf = (lane >> 4) * 16;

    float acc[4][8][4];
#pragma unroll
    for (int i = 0; i < 4; i++)
#pragma unroll
        for (int j = 0; j < 8; j++)
#pragma unroll
            for (int q = 0; q < 4; q++) acc[i][j][q] = 0.f;

    const __nv_bfloat16* Abase = g_A  + (size_t)(m0 + lrow) * KTOT + lcol * 8;
    const __nv_bfloat16* Bbase = g_Wc + (size_t)(n0 + lrow) * KTOT + lcol * 8;

    auto load_stage = [&](uint32_t st, int chunk) {
        const __nv_bfloat16* Ap = Abase + chunk * BK;
        const __nv_bfloat16* Bp = Bbase + chunk * BK;
#pragma unroll
        for (int j = 0; j < 8; j++) {   // A: 128 rows x 128B, 16-row steps
            int r = lrow + 16 * j;
            cp_async16(st + SW128(r * 128 + lcol * 16), Ap + (size_t)(16 * j) * KTOT);
        }
#pragma unroll
        for (int j = 0; j < 8; j++) {   // B: 128 rows x 128B
            int r = lrow + 16 * j;
            cp_async16(st + 16384 + SW128(r * 128 + lcol * 16), Bp + (size_t)(16 * j) * KTOT);
        }
        cp_commit();
    };

    uint32_t af[2][4][4], bf[2][4][4];

    auto prefetch = [&](uint32_t stA, int ks, int buf) {
        const uint32_t stB = stA + 16384;
        const int kb = ks * 32 + lkhalf;
#pragma unroll
        for (int i = 0; i < 4; i++)
            ldm_x4(af[buf][i], stA + SW128((mwarp + i * 16 + lrow16) * 128 + kb));
#pragma unroll
        for (int j = 0; j < 4; j++)
            ldm_x4(bf[buf][j], stB + SW128((nwarp + j * 16 + lrow16) * 128 + kb));
    };

    uint32_t sCur  = smem_base;
    uint32_t sNext = smem_base + STAGE_BYTES;
    uint32_t sLoad = smem_base + 2 * STAGE_BYTES;

    load_stage(sCur, 0);
    load_stage(sNext, 1);

    cp_wait<1>();          // chunk 0 ready
    __syncthreads();
    prefetch(sCur, 0, 0);  // chunk 0, ks=0

    for (int c = 0; c < NK_CHUNKS; c++) {
        if (c + 2 < NK_CHUNKS) load_stage(sLoad, c + 2);

#pragma unroll
        for (int ks = 0; ks < 4; ks++) {
            const int cur = ks & 1, nxt = cur ^ 1;
            if (ks < 3) prefetch(sCur, ks + 1, nxt);
#pragma unroll
            for (int i = 0; i < 4; i++)
#pragma unroll
                for (int j = 0; j < 4; j++) {
                    mma16816(acc[i][j * 2 + 0], af[cur][i], bf[cur][j][0], bf[cur][j][2]);
                    mma16816(acc[i][j * 2 + 1], af[cur][i], bf[cur][j][1], bf[cur][j][3]);
                }
        }

        if (c + 1 < NK_CHUNKS) {
            if (c + 2 < NK_CHUNKS) cp_wait<1>(); else cp_wait<0>();
            __syncthreads();
            prefetch(sNext, 0, 0);
        }
        uint32_t t = sCur; sCur = sNext; sNext = sLoad; sLoad = t;
    }

    // fused epilogue: out = acc + bias~ + residual-mix of x.
    const int erow = lane >> 2;
    const int ecol = (lane & 3) * 2;
    const int tlo = nwarp >> 5;
#pragma unroll
    for (int j = 0; j < 4; j++) {
        const int colT = nwarp + j * 8 + ecol;
        const int dd = dd0 + (colT & 31);
        const float2 bv0 = *(const float2*)(g_bias + n0 + colT);
        const float2 bv1 = *(const float2*)(g_bias + n0 + colT + 32);
        float rw0[4], rw1[4];
#pragma unroll
        for (int s = 0; s < 4; s++) { rw0[s] = g_sm.Rw[s][tlo]; rw1[s] = g_sm.Rw[s][tlo + 1]; }
#pragma unroll
        for (int i = 0; i < 4; i++) {
#pragma unroll
            for (int rr = 0; rr < 2; rr++) {
                const int m = m0 + mwarp + i * 16 + erow + rr * 8;
                const float* xr = x + (size_t)m * DD + dd;
                float2 xv[4];
#pragma unroll
                for (int s = 0; s < 4; s++) xv[s] = __ldg((const float2*)(xr + s * SD));
                float o0 = acc[i][j][rr * 2 + 0] + bv0.x;
                float o1 = acc[i][j][rr * 2 + 1] + bv0.y;
                float p0 = acc[i][j + 4][rr * 2 + 0] + bv1.x;
                float p1 = acc[i][j + 4][rr * 2 + 1] + bv1.y;
#pragma unroll
                for (int s = 0; s < 4; s++) {
                    o0 += rw0[s] * xv[s].x;  o1 += rw0[s] * xv[s].y;
                    p0 += rw1[s] * xv[s].x;  p1 += rw1[s] * xv[s].y;
                }
                float* ob = out + (size_t)m * DD + tlo * SD + dd;
                *(float2*)ob = make_float2(o0, o1);
                *(float2*)(ob + SD) = make_float2(p0, p1);
            }
        }
    }
}

// ---------------- launch ----------------
extern "C" void kernel_launch(void* const* d_in, const int* in_sizes, int n_in,
                              void* d_out, int out_size) {
    const float* x     = (const float*)d_in[0];
    const float* g     = (const float*)d_in[1];
    const float* b     = (const float*)d_in[2];
    const float* Wa    = (const float*)d_in[3];
    const float* ba    = (const float*)d_in[4];
    const float* Wh    = (const float*)d_in[5];
    const float* bh    = (const float*)d_in[6];
    const float* pre_a = (const float*)d_in[7];
    const float* pre_h = (const float*)d_in[8];
    const float* res_a = (const float*)d_in[9];
    const float* post_a= (const float*)d_in[10];
    const float* sc_a  = (const float*)d_in[11];
    const float* res_h = (const float*)d_in[12];
    const float* post_h= (const float*)d_in[13];
    const float* sc_h  = (const float*)d_in[14];
    const float* cm    = (const float*)d_in[15];
    float* out = (float*)d_out;

    cudaFuncSetAttribute(gemm_kernel, cudaFuncAttributeMaxDynamicSharedMemorySize, DYN_SMEM);

    small_kernel<<<1, 256>>>(pre_a, pre_h, res_a, post_a, sc_a,
                             res_h, post_h, sc_h, cm, ba, bh);
    prep_kernel<<<MROWS + WT_BLOCKS, 256>>>(x, g, b, Wa, Wh);
    gemm_kernel<<<dim3(16, 128), 128, DYN_SMEM>>>(x, out);
}